// round 9
// baseline (speedup 1.0000x reference)
#include <cuda_runtime.h>
#include <cuda_bf16.h>
#include <cuda_fp16.h>
#include <mma.h>
#include <math.h>

using namespace nvcuda;

// ---------------- problem constants ----------------
#define NL 2          // layers
#define NB 4          // batch
#define NT 64         // time
#define ND 512        // input dim
#define NH 512        // hidden/proj dim
#define NC 4096       // cell dim
#define NG (4*NC)     // 16384 gate rows per dir
#define CLIPV 3.0f
#define WS_ELEMS ((size_t)2 * NG * ND)   // 16,777,216 per layer
#define WP_ELEMS ((size_t)2 * NH * NC)   //  4,194,304 per layer

// ---------------- device scratch (static allocation: allowed) ----------------
__device__ __align__(16) float g_pi[(size_t)2 * NB * NT * NG];   // [dir][b][t][g]  32 MiB
__device__ __align__(16) float g_x [(size_t)2 * NB * NT * NH];   // layer input
__device__ __align__(16) float g_y [(size_t)2 * NB * NT * NH];   // layer raw out
__device__ __align__(16) float g_s [(size_t)2 * NB * NC];        // sigma(o)*tanh(c_new)
__device__ __align__(16) float g_c [(size_t)2 * NB * NC];        // cell state
__device__ __align__(16) float g_h [(size_t)2 * NB * NH];        // hidden state
// fp16 weight copies for the current layer (streamed every step)
__device__ __align__(16) __half g_wsh[WS_ELEMS];                 // 33.5 MB
__device__ __align__(16) __half g_wph[WP_ELEMS];                 //  8.4 MB
// proj k-split partials + arrival counters (R4 scheme; counters self-reset)
__device__ __align__(16) float g_pp[(size_t)2 * NH * NB * 8];
__device__ int g_cnt[2 * 64];

__device__ __forceinline__ float sigmoidf_(float x) { return 1.0f / (1.0f + expf(-x)); }
__device__ __forceinline__ float clip3(float x)     { return fminf(CLIPV, fmaxf(-CLIPV, x)); }

// dot of 8 fp16 weights (as uint4) with 8 fp32 values (two float4)
__device__ __forceinline__ float dot8h(uint4 wv, float4 ha, float4 hb) {
    float2 w0 = __half22float2(*(const __half2*)&wv.x);
    float2 w1 = __half22float2(*(const __half2*)&wv.y);
    float2 w2 = __half22float2(*(const __half2*)&wv.z);
    float2 w3 = __half22float2(*(const __half2*)&wv.w);
    return w0.x*ha.x + w0.y*ha.y + w1.x*ha.z + w1.y*ha.w
         + w2.x*hb.x + w2.y*hb.y + w3.x*hb.z + w3.y*hb.w;
}

// ---------------- init: zero h and c (reference resets per layer/direction) ----
__global__ void init_state_kernel() {
    int idx = blockIdx.x * blockDim.x + threadIdx.x;
    if (idx < 2 * NB * NC) g_c[idx] = 0.0f;
    if (idx < 2 * NB * NH) g_h[idx] = 0.0f;
}

// ---------------- weight conversion: fp32 -> fp16 for this layer ---------------
__global__ void __launch_bounds__(256)
convert_weights_kernel(const float* __restrict__ Ws_l, const float* __restrict__ Wp_l)
{
    size_t idx = ((size_t)blockIdx.x * blockDim.x + threadIdx.x) * 8;
    const float* src;
    __half* dst;
    if (idx < WS_ELEMS) {
        src = Ws_l + idx;           dst = g_wsh + idx;
    } else {
        size_t i2 = idx - WS_ELEMS;
        if (i2 >= WP_ELEMS) return;
        src = Wp_l + i2;            dst = g_wph + i2;
    }
    float4 a = __ldcs((const float4*)src);
    float4 b = __ldcs((const float4*)(src + 4));
    __half2 h0 = __floats2half2_rn(a.x, a.y);
    __half2 h1 = __floats2half2_rn(a.z, a.w);
    __half2 h2 = __floats2half2_rn(b.x, b.y);
    __half2 h3 = __floats2half2_rn(b.z, b.w);
    uint4 u;
    u.x = *(const unsigned*)&h0; u.y = *(const unsigned*)&h1;
    u.z = *(const unsigned*)&h2; u.w = *(const unsigned*)&h3;
    *(uint4*)dst = u;
}

// ---------------- pi GEMM: pi[d][m][n] = A[m,:] . Wi[n,:]  (split-bf16, 3 MMAs) ----
__global__ void __launch_bounds__(256)
pi_kernel(const float* __restrict__ x0, const float* __restrict__ Wi_l, int l)
{
    const int d = blockIdx.z;
    const float* A  = l ? (g_x + (size_t)d * (NB * NT * NH)) : x0;
    const float* Bg = Wi_l + (size_t)d * NG * ND;
    const int mBase = blockIdx.y * 128;
    const int nBase = blockIdx.x * 64;

    __shared__ __nv_bfloat16 As[2][128][40];
    __shared__ __nv_bfloat16 Bs[2][64][40];

    wmma::fragment<wmma::accumulator, 16, 16, 16, float> acc[2][2];
#pragma unroll
    for (int i = 0; i < 2; i++)
#pragma unroll
        for (int j = 0; j < 2; j++) wmma::fill_fragment(acc[i][j], 0.0f);

    const int w  = threadIdx.x >> 5;
    const int wm = w >> 1;
    const int wn = w & 1;

    for (int kk = 0; kk < 16; kk++) {
        const int k0 = kk * 32;
#pragma unroll
        for (int rpt = 0; rpt < 4; rpt++) {
            int id = threadIdx.x + rpt * 256;
            int r = id >> 3, c = (id & 7) << 2;
            float4 v = *(const float4*)(A + (size_t)(mBase + r) * ND + k0 + c);
            float vs[4] = {v.x, v.y, v.z, v.w};
#pragma unroll
            for (int q = 0; q < 4; q++) {
                __nv_bfloat16 hi = __float2bfloat16(vs[q]);
                As[0][r][c + q] = hi;
                As[1][r][c + q] = __float2bfloat16(vs[q] - __bfloat162float(hi));
            }
        }
#pragma unroll
        for (int rpt = 0; rpt < 2; rpt++) {
            int id = threadIdx.x + rpt * 256;
            int r = id >> 3, c = (id & 7) << 2;
            float4 v = *(const float4*)(Bg + (size_t)(nBase + r) * ND + k0 + c);
            float vs[4] = {v.x, v.y, v.z, v.w};
#pragma unroll
            for (int q = 0; q < 4; q++) {
                __nv_bfloat16 hi = __float2bfloat16(vs[q]);
                Bs[0][r][c + q] = hi;
                Bs[1][r][c + q] = __float2bfloat16(vs[q] - __bfloat162float(hi));
            }
        }
        __syncthreads();

#pragma unroll
        for (int ks = 0; ks < 2; ks++) {
            wmma::fragment<wmma::matrix_a, 16, 16, 16, __nv_bfloat16, wmma::row_major> ah[2], al[2];
            wmma::fragment<wmma::matrix_b, 16, 16, 16, __nv_bfloat16, wmma::col_major> bh[2], bl[2];
#pragma unroll
            for (int i = 0; i < 2; i++) {
                wmma::load_matrix_sync(ah[i], &As[0][wm * 32 + i * 16][ks * 16], 40);
                wmma::load_matrix_sync(al[i], &As[1][wm * 32 + i * 16][ks * 16], 40);
            }
#pragma unroll
            for (int j = 0; j < 2; j++) {
                wmma::load_matrix_sync(bh[j], &Bs[0][wn * 32 + j * 16][ks * 16], 40);
                wmma::load_matrix_sync(bl[j], &Bs[1][wn * 32 + j * 16][ks * 16], 40);
            }
#pragma unroll
            for (int i = 0; i < 2; i++)
#pragma unroll
                for (int j = 0; j < 2; j++) {
                    wmma::mma_sync(acc[i][j], ah[i], bh[j], acc[i][j]);
                    wmma::mma_sync(acc[i][j], ah[i], bl[j], acc[i][j]);
                    wmma::mma_sync(acc[i][j], al[i], bh[j], acc[i][j]);
                }
        }
        __syncthreads();
    }

#pragma unroll
    for (int i = 0; i < 2; i++)
#pragma unroll
        for (int j = 0; j < 2; j++) {
            float* cp = g_pi + ((size_t)d * (NB * NT) + mBase + wm * 32 + i * 16) * NG
                             + nBase + wn * 32 + j * 16;
            wmma::store_matrix_sync(cp, acc[i][j], NG, wmma::mem_row_major);
        }
}

// ---------------- step 1: gates + cell update (fp16 weights, fp32 accum) -------
// R4 layout: grid 1024, block -> (dir, 8 cells), warp -> cell j, lane covers 8 k.
__global__ void __launch_bounds__(256)
step_gates_kernel(const float* __restrict__ bs_l,   // (2, 16384)
                  const int*   __restrict__ mask, int t)
{
    __shared__ float sh[NB * NH];
    const int d  = blockIdx.x >> 9;
    const int cb = (blockIdx.x & 511) * 8;
    const int td = d ? (NT - 1 - t) : t;
    const int tid = threadIdx.x;

    const float* hsrc = g_h + (size_t)d * NB * NH;
    for (int i = tid; i < NB * NH; i += 256) sh[i] = hsrc[i];
    __syncthreads();

    const int w = tid >> 5, lane = tid & 31;
    const int j = cb + w;
    const __half* wbase = g_wsh + (size_t)d * NG * ND;

    float acc[4][4];
#pragma unroll
    for (int q = 0; q < 4; q++)
#pragma unroll
        for (int b = 0; b < 4; b++) acc[q][b] = 0.0f;

#pragma unroll
    for (int it = 0; it < 2; it++) {
        const int k = it * 256 + lane * 8;
        float4 ha0 = *(const float4*)&sh[0 * NH + k], hb0 = *(const float4*)&sh[0 * NH + k + 4];
        float4 ha1 = *(const float4*)&sh[1 * NH + k], hb1 = *(const float4*)&sh[1 * NH + k + 4];
        float4 ha2 = *(const float4*)&sh[2 * NH + k], hb2 = *(const float4*)&sh[2 * NH + k + 4];
        float4 ha3 = *(const float4*)&sh[3 * NH + k], hb3 = *(const float4*)&sh[3 * NH + k + 4];
#pragma unroll
        for (int q = 0; q < 4; q++) {
            uint4 wv = *(const uint4*)&wbase[(size_t)(q * NC + j) * ND + k];
            acc[q][0] += dot8h(wv, ha0, hb0);
            acc[q][1] += dot8h(wv, ha1, hb1);
            acc[q][2] += dot8h(wv, ha2, hb2);
            acc[q][3] += dot8h(wv, ha3, hb3);
        }
    }
#pragma unroll
    for (int off = 16; off > 0; off >>= 1)
#pragma unroll
        for (int q = 0; q < 4; q++)
#pragma unroll
            for (int b = 0; b < 4; b++)
                acc[q][b] += __shfl_xor_sync(0xffffffffu, acc[q][b], off);

    if (lane < 4) {
        const int b = lane;
        const float* pib = g_pi + (((size_t)d * NB + b) * NT + td) * NG;
        const float* bsd = bs_l + (size_t)d * NG;
        float gi = acc[0][b] + __ldcs(&pib[0 * NC + j]) + bsd[0 * NC + j];
        float gf = acc[1][b] + __ldcs(&pib[1 * NC + j]) + bsd[1 * NC + j];
        float gg = acc[2][b] + __ldcs(&pib[2 * NC + j]) + bsd[2 * NC + j];
        float go = acc[3][b] + __ldcs(&pib[3 * NC + j]) + bsd[3 * NC + j];

        const size_t ci = ((size_t)d * NB + b) * NC + j;
        float cold = g_c[ci];
        float cn = clip3(sigmoidf_(gi) * tanhf(gg) + sigmoidf_(gf) * cold);
        if (mask[b * NT + td] != 0) g_c[ci] = cn;
        g_s[ci] = sigmoidf_(go) * tanhf(cn);
    }
}

// ---------------- step 2: h_new = clip(s @ Wp^T)  (R4 K-split, fp16 Wp) --------
__global__ void __launch_bounds__(256)
step_proj_kernel(const int* __restrict__ mask, int t)
{
    const int d  = blockIdx.x >> 9;
    const int ig = (blockIdx.x >> 3) & 63;
    const int kc = blockIdx.x & 7;
    const int td = d ? (NT - 1 - t) : t;

    __shared__ float ss[NB * 512];
    const float* sbase = g_s + (size_t)d * NB * NC + kc * 512;
    for (int idx = threadIdx.x; idx < NB * 512; idx += 256) {
        int b = idx >> 9, k = idx & 511;
        ss[idx] = sbase[(size_t)b * NC + k];
    }
    __syncthreads();

    const int w = threadIdx.x >> 5, lane = threadIdx.x & 31;
    const int iOut = ig * 8 + w;
    const __half* wrow = g_wph + ((size_t)d * NH + iOut) * NC + kc * 512;

    float acc[4] = {0.f, 0.f, 0.f, 0.f};
#pragma unroll
    for (int it = 0; it < 2; it++) {
        const int k = it * 256 + lane * 8;
        uint4 wv = *(const uint4*)&wrow[k];
        acc[0] += dot8h(wv, *(const float4*)&ss[0 * 512 + k], *(const float4*)&ss[0 * 512 + k + 4]);
        acc[1] += dot8h(wv, *(const float4*)&ss[1 * 512 + k], *(const float4*)&ss[1 * 512 + k + 4]);
        acc[2] += dot8h(wv, *(const float4*)&ss[2 * 512 + k], *(const float4*)&ss[2 * 512 + k + 4]);
        acc[3] += dot8h(wv, *(const float4*)&ss[3 * 512 + k], *(const float4*)&ss[3 * 512 + k + 4]);
    }
#pragma unroll
    for (int off = 16; off > 0; off >>= 1)
#pragma unroll
        for (int b = 0; b < 4; b++)
            acc[b] += __shfl_xor_sync(0xffffffffu, acc[b], off);

    if (lane < 4)
        g_pp[(((size_t)d * NH + iOut) * NB + lane) * 8 + kc] = acc[lane];

    __threadfence();
    __syncthreads();
    __shared__ int isLast;
    if (threadIdx.x == 0)
        isLast = (atomicAdd(&g_cnt[d * 64 + ig], 1) == 7);
    __syncthreads();
    if (!isLast) return;

    if (threadIdx.x < 32) {
        const int wi = threadIdx.x >> 2;
        const int b  = threadIdx.x & 3;
        const int io = ig * 8 + wi;
        const float* pp = &g_pp[(((size_t)d * NH + io) * NB + b) * 8];
        float v = 0.0f;
#pragma unroll
        for (int c = 0; c < 8; c++) v += __ldcg(&pp[c]);
        v = clip3(v);
        const size_t yi = (((size_t)d * NB + b) * NT + td) * NH + io;
        if (mask[b * NT + td] != 0) {
            g_h[((size_t)d * NB + b) * NH + io] = v;
            g_y[yi] = v;
        } else {
            g_y[yi] = 0.0f;
        }
    }
    if (threadIdx.x == 0) g_cnt[d * 64 + ig] = 0;
}

// ---------------- finalize layer: skip-add, write output, feed next layer ------
__global__ void __launch_bounds__(512)
finalize_kernel(float* __restrict__ out, int l)
{
    const int idx = blockIdx.x * blockDim.x + threadIdx.x;   // 0 .. 262143
    const int i  = idx & (NH - 1);
    const int tt = (idx >> 9) & (NT - 1);
    const int b  = (idx >> 15) & (NB - 1);
    const int d  = idx >> 17;
    float z = g_y[idx] + (l ? g_x[idx] : 0.0f);
    g_x[idx] = z;
    out[(((size_t)l * NB + b) * NT + tt) * (2 * NH) + d * NH + i] = z;
}

// ---------------- launcher ----------------
extern "C" void kernel_launch(void* const* d_in, const int* in_sizes, int n_in,
                              void* d_out, int out_size)
{
    const float* inputs = (const float*)d_in[0];   // (4,64,512)
    const int*   mask   = (const int*)  d_in[1];   // (4,64)
    const float* Wi     = (const float*)d_in[2];   // (2,2,16384,512)
    const float* Ws     = (const float*)d_in[3];   // (2,2,16384,512)
    const float* bs     = (const float*)d_in[4];   // (2,2,16384)
    const float* Wp     = (const float*)d_in[5];   // (2,2,512,4096)
    float* out = (float*)d_out;                    // (2,4,64,1024)

    const int convBlocks = (int)((WS_ELEMS + WP_ELEMS) / 8 / 256);   // 10240

    for (int l = 0; l < NL; l++) {
        const float* Wi_l = Wi + (size_t)l * 2 * NG * ND;
        const float* Ws_l = Ws + (size_t)l * 2 * NG * ND;
        const float* bs_l = bs + (size_t)l * 2 * NG;
        const float* Wp_l = Wp + (size_t)l * 2 * NH * NC;

        init_state_kernel<<<144, 256>>>();                         // per-layer reset
        convert_weights_kernel<<<convBlocks, 256>>>(Ws_l, Wp_l);   // fp32 -> fp16

        dim3 gp(NG / 64, (NB * NT) / 128, 2);
        pi_kernel<<<gp, 256>>>(inputs, Wi_l, l);

        for (int t = 0; t < NT; t++) {
            step_gates_kernel<<<1024, 256>>>(bs_l, mask, t);
            step_proj_kernel<<<1024, 256>>>(mask, t);
        }
        finalize_kernel<<<512, 512>>>(out, l);
    }
}

// round 10
// speedup vs baseline: 1.0827x; 1.0827x over previous
#include <cuda_runtime.h>
#include <cuda_bf16.h>
#include <cuda_fp16.h>
#include <mma.h>
#include <math.h>

using namespace nvcuda;

// ---------------- problem constants ----------------
#define NL 2          // layers
#define NB 4          // batch
#define NT 64         // time
#define ND 512        // input dim
#define NH 512        // hidden/proj dim
#define NC 4096       // cell dim
#define NG (4*NC)     // 16384 gate rows per dir
#define CLIPV 3.0f
#define WP_ELEMS ((size_t)2 * NH * NC)   // 4,194,304 per layer

// ---------------- device scratch (static allocation: allowed) ----------------
__device__ __align__(16) float g_pi[(size_t)2 * NB * NT * NG];   // [dir][b][t][g]  32 MiB
__device__ __align__(16) float g_x [(size_t)2 * NB * NT * NH];   // layer input
__device__ __align__(16) float g_y [(size_t)2 * NB * NT * NH];   // layer raw out
__device__ __align__(16) float g_s [(size_t)2 * NB * NC];        // sigma(o)*tanh(c_new)
__device__ __align__(16) float g_c [(size_t)2 * NB * NC];        // cell state
__device__ __align__(16) float g_h [(size_t)2 * NB * NH];        // hidden state
// fp16 Wp copy for the current layer (proj weight stream halved)
__device__ __align__(16) __half g_wph[WP_ELEMS];                 // 8.4 MB
// proj k-split partials + arrival counters (R4 scheme; counters self-reset)
__device__ __align__(16) float g_pp[(size_t)2 * NH * NB * 8];
__device__ int g_cnt[2 * 64];

__device__ __forceinline__ float dot4(float4 a, float4 b) {
    return a.x*b.x + a.y*b.y + a.z*b.z + a.w*b.w;
}
__device__ __forceinline__ float sigmoidf_(float x) { return 1.0f / (1.0f + expf(-x)); }
__device__ __forceinline__ float clip3(float x)     { return fminf(CLIPV, fmaxf(-CLIPV, x)); }

// dot of 8 fp16 weights (as uint4) with 8 fp32 values (two float4)
__device__ __forceinline__ float dot8h(uint4 wv, float4 ha, float4 hb) {
    float2 w0 = __half22float2(*(const __half2*)&wv.x);
    float2 w1 = __half22float2(*(const __half2*)&wv.y);
    float2 w2 = __half22float2(*(const __half2*)&wv.z);
    float2 w3 = __half22float2(*(const __half2*)&wv.w);
    return w0.x*ha.x + w0.y*ha.y + w1.x*ha.z + w1.y*ha.w
         + w2.x*hb.x + w2.y*hb.y + w3.x*hb.z + w3.y*hb.w;
}

// ---------------- init: zero h and c (reference resets per layer/direction) ----
__global__ void init_state_kernel() {
    int idx = blockIdx.x * blockDim.x + threadIdx.x;
    if (idx < 2 * NB * NC) g_c[idx] = 0.0f;
    if (idx < 2 * NB * NH) g_h[idx] = 0.0f;
}

// ---------------- weight conversion: Wp fp32 -> fp16 for this layer ------------
__global__ void __launch_bounds__(256)
convert_wp_kernel(const float* __restrict__ Wp_l)
{
    size_t idx = ((size_t)blockIdx.x * blockDim.x + threadIdx.x) * 8;
    if (idx >= WP_ELEMS) return;
    float4 a = __ldcs((const float4*)(Wp_l + idx));
    float4 b = __ldcs((const float4*)(Wp_l + idx + 4));
    __half2 h0 = __floats2half2_rn(a.x, a.y);
    __half2 h1 = __floats2half2_rn(a.z, a.w);
    __half2 h2 = __floats2half2_rn(b.x, b.y);
    __half2 h3 = __floats2half2_rn(b.z, b.w);
    uint4 u;
    u.x = *(const unsigned*)&h0; u.y = *(const unsigned*)&h1;
    u.z = *(const unsigned*)&h2; u.w = *(const unsigned*)&h3;
    *(uint4*)(g_wph + idx) = u;
}

// ---------------- pi GEMM: pi[d][m][n] = A[m,:] . Wi[n,:]  (split-bf16, 3 MMAs) ----
__global__ void __launch_bounds__(256)
pi_kernel(const float* __restrict__ x0, const float* __restrict__ Wi_l, int l)
{
    const int d = blockIdx.z;
    const float* A  = l ? (g_x + (size_t)d * (NB * NT * NH)) : x0;
    const float* Bg = Wi_l + (size_t)d * NG * ND;
    const int mBase = blockIdx.y * 128;
    const int nBase = blockIdx.x * 64;

    __shared__ __nv_bfloat16 As[2][128][40];
    __shared__ __nv_bfloat16 Bs[2][64][40];

    wmma::fragment<wmma::accumulator, 16, 16, 16, float> acc[2][2];
#pragma unroll
    for (int i = 0; i < 2; i++)
#pragma unroll
        for (int j = 0; j < 2; j++) wmma::fill_fragment(acc[i][j], 0.0f);

    const int w  = threadIdx.x >> 5;
    const int wm = w >> 1;
    const int wn = w & 1;

    for (int kk = 0; kk < 16; kk++) {
        const int k0 = kk * 32;
#pragma unroll
        for (int rpt = 0; rpt < 4; rpt++) {
            int id = threadIdx.x + rpt * 256;
            int r = id >> 3, c = (id & 7) << 2;
            float4 v = *(const float4*)(A + (size_t)(mBase + r) * ND + k0 + c);
            float vs[4] = {v.x, v.y, v.z, v.w};
#pragma unroll
            for (int q = 0; q < 4; q++) {
                __nv_bfloat16 hi = __float2bfloat16(vs[q]);
                As[0][r][c + q] = hi;
                As[1][r][c + q] = __float2bfloat16(vs[q] - __bfloat162float(hi));
            }
        }
#pragma unroll
        for (int rpt = 0; rpt < 2; rpt++) {
            int id = threadIdx.x + rpt * 256;
            int r = id >> 3, c = (id & 7) << 2;
            float4 v = *(const float4*)(Bg + (size_t)(nBase + r) * ND + k0 + c);
            float vs[4] = {v.x, v.y, v.z, v.w};
#pragma unroll
            for (int q = 0; q < 4; q++) {
                __nv_bfloat16 hi = __float2bfloat16(vs[q]);
                Bs[0][r][c + q] = hi;
                Bs[1][r][c + q] = __float2bfloat16(vs[q] - __bfloat162float(hi));
            }
        }
        __syncthreads();

#pragma unroll
        for (int ks = 0; ks < 2; ks++) {
            wmma::fragment<wmma::matrix_a, 16, 16, 16, __nv_bfloat16, wmma::row_major> ah[2], al[2];
            wmma::fragment<wmma::matrix_b, 16, 16, 16, __nv_bfloat16, wmma::col_major> bh[2], bl[2];
#pragma unroll
            for (int i = 0; i < 2; i++) {
                wmma::load_matrix_sync(ah[i], &As[0][wm * 32 + i * 16][ks * 16], 40);
                wmma::load_matrix_sync(al[i], &As[1][wm * 32 + i * 16][ks * 16], 40);
            }
#pragma unroll
            for (int j = 0; j < 2; j++) {
                wmma::load_matrix_sync(bh[j], &Bs[0][wn * 32 + j * 16][ks * 16], 40);
                wmma::load_matrix_sync(bl[j], &Bs[1][wn * 32 + j * 16][ks * 16], 40);
            }
#pragma unroll
            for (int i = 0; i < 2; i++)
#pragma unroll
                for (int j = 0; j < 2; j++) {
                    wmma::mma_sync(acc[i][j], ah[i], bh[j], acc[i][j]);
                    wmma::mma_sync(acc[i][j], ah[i], bl[j], acc[i][j]);
                    wmma::mma_sync(acc[i][j], al[i], bh[j], acc[i][j]);
                }
        }
        __syncthreads();
    }

#pragma unroll
    for (int i = 0; i < 2; i++)
#pragma unroll
        for (int j = 0; j < 2; j++) {
            float* cp = g_pi + ((size_t)d * (NB * NT) + mBase + wm * 32 + i * 16) * NG
                             + nBase + wn * 32 + j * 16;
            wmma::store_matrix_sync(cp, acc[i][j], NG, wmma::mem_row_major);
        }
}

// ---------------- step 1: gates + cell update (R4 fp32 version, verbatim) ------
__global__ void __launch_bounds__(256)
step_gates_kernel(const float* __restrict__ Ws_l,   // (2, 16384, 512)
                  const float* __restrict__ bs_l,   // (2, 16384)
                  const int*   __restrict__ mask, int t)
{
    __shared__ float sh[NB * NH];
    const int d  = blockIdx.x >> 9;
    const int cb = (blockIdx.x & 511) * 8;
    const int td = d ? (NT - 1 - t) : t;
    const int tid = threadIdx.x;

    const float* hsrc = g_h + (size_t)d * NB * NH;
    for (int i = tid; i < NB * NH; i += 256) sh[i] = hsrc[i];
    __syncthreads();

    const int w = tid >> 5, lane = tid & 31;
    const int j = cb + w;
    const float* wbase = Ws_l + (size_t)d * NG * ND;

    float acc[4][4];
#pragma unroll
    for (int q = 0; q < 4; q++)
#pragma unroll
        for (int b = 0; b < 4; b++) acc[q][b] = 0.0f;

#pragma unroll
    for (int it = 0; it < 4; it++) {
        const int k = it * 128 + lane * 4;
        float4 hv0 = *(const float4*)&sh[0 * NH + k];
        float4 hv1 = *(const float4*)&sh[1 * NH + k];
        float4 hv2 = *(const float4*)&sh[2 * NH + k];
        float4 hv3 = *(const float4*)&sh[3 * NH + k];
#pragma unroll
        for (int q = 0; q < 4; q++) {
            float4 wv = *(const float4*)&wbase[(size_t)(q * NC + j) * ND + k];
            acc[q][0] += dot4(wv, hv0);
            acc[q][1] += dot4(wv, hv1);
            acc[q][2] += dot4(wv, hv2);
            acc[q][3] += dot4(wv, hv3);
        }
    }
#pragma unroll
    for (int off = 16; off > 0; off >>= 1)
#pragma unroll
        for (int q = 0; q < 4; q++)
#pragma unroll
            for (int b = 0; b < 4; b++)
                acc[q][b] += __shfl_xor_sync(0xffffffffu, acc[q][b], off);

    if (lane < 4) {
        const int b = lane;
        const float* pib = g_pi + (((size_t)d * NB + b) * NT + td) * NG;
        const float* bsd = bs_l + (size_t)d * NG;
        float gi = acc[0][b] + __ldcs(&pib[0 * NC + j]) + bsd[0 * NC + j];
        float gf = acc[1][b] + __ldcs(&pib[1 * NC + j]) + bsd[1 * NC + j];
        float gg = acc[2][b] + __ldcs(&pib[2 * NC + j]) + bsd[2 * NC + j];
        float go = acc[3][b] + __ldcs(&pib[3 * NC + j]) + bsd[3 * NC + j];

        const size_t ci = ((size_t)d * NB + b) * NC + j;
        float cold = g_c[ci];
        float cn = clip3(sigmoidf_(gi) * tanhf(gg) + sigmoidf_(gf) * cold);
        if (mask[b * NT + td] != 0) g_c[ci] = cn;
        g_s[ci] = sigmoidf_(go) * tanhf(cn);
    }
}

// ---------------- step 2: h_new = clip(s @ Wp^T)  (R4 K-split + fp16 Wp) -------
__global__ void __launch_bounds__(256)
step_proj_kernel(const int* __restrict__ mask, int t)
{
    const int d  = blockIdx.x >> 9;
    const int ig = (blockIdx.x >> 3) & 63;
    const int kc = blockIdx.x & 7;
    const int td = d ? (NT - 1 - t) : t;

    __shared__ float ss[NB * 512];
    const float* sbase = g_s + (size_t)d * NB * NC + kc * 512;
    for (int idx = threadIdx.x; idx < NB * 512; idx += 256) {
        int b = idx >> 9, k = idx & 511;
        ss[idx] = sbase[(size_t)b * NC + k];
    }
    __syncthreads();

    const int w = threadIdx.x >> 5, lane = threadIdx.x & 31;
    const int iOut = ig * 8 + w;
    const __half* wrow = g_wph + ((size_t)d * NH + iOut) * NC + kc * 512;

    float acc[4] = {0.f, 0.f, 0.f, 0.f};
#pragma unroll
    for (int it = 0; it < 2; it++) {
        const int k = it * 256 + lane * 8;
        uint4 wv = *(const uint4*)&wrow[k];
        acc[0] += dot8h(wv, *(const float4*)&ss[0 * 512 + k], *(const float4*)&ss[0 * 512 + k + 4]);
        acc[1] += dot8h(wv, *(const float4*)&ss[1 * 512 + k], *(const float4*)&ss[1 * 512 + k + 4]);
        acc[2] += dot8h(wv, *(const float4*)&ss[2 * 512 + k], *(const float4*)&ss[2 * 512 + k + 4]);
        acc[3] += dot8h(wv, *(const float4*)&ss[3 * 512 + k], *(const float4*)&ss[3 * 512 + k + 4]);
    }
#pragma unroll
    for (int off = 16; off > 0; off >>= 1)
#pragma unroll
        for (int b = 0; b < 4; b++)
            acc[b] += __shfl_xor_sync(0xffffffffu, acc[b], off);

    if (lane < 4)
        g_pp[(((size_t)d * NH + iOut) * NB + lane) * 8 + kc] = acc[lane];

    __threadfence();
    __syncthreads();
    __shared__ int isLast;
    if (threadIdx.x == 0)
        isLast = (atomicAdd(&g_cnt[d * 64 + ig], 1) == 7);
    __syncthreads();
    if (!isLast) return;

    if (threadIdx.x < 32) {
        const int wi = threadIdx.x >> 2;
        const int b  = threadIdx.x & 3;
        const int io = ig * 8 + wi;
        const float* pp = &g_pp[(((size_t)d * NH + io) * NB + b) * 8];
        float v = 0.0f;
#pragma unroll
        for (int c = 0; c < 8; c++) v += __ldcg(&pp[c]);
        v = clip3(v);
        const size_t yi = (((size_t)d * NB + b) * NT + td) * NH + io;
        if (mask[b * NT + td] != 0) {
            g_h[((size_t)d * NB + b) * NH + io] = v;
            g_y[yi] = v;
        } else {
            g_y[yi] = 0.0f;
        }
    }
    if (threadIdx.x == 0) g_cnt[d * 64 + ig] = 0;
}

// ---------------- finalize layer: skip-add, write output, feed next layer ------
__global__ void __launch_bounds__(512)
finalize_kernel(float* __restrict__ out, int l)
{
    const int idx = blockIdx.x * blockDim.x + threadIdx.x;   // 0 .. 262143
    const int i  = idx & (NH - 1);
    const int tt = (idx >> 9) & (NT - 1);
    const int b  = (idx >> 15) & (NB - 1);
    const int d  = idx >> 17;
    float z = g_y[idx] + (l ? g_x[idx] : 0.0f);
    g_x[idx] = z;
    out[(((size_t)l * NB + b) * NT + tt) * (2 * NH) + d * NH + i] = z;
}

// ---------------- launcher ----------------
extern "C" void kernel_launch(void* const* d_in, const int* in_sizes, int n_in,
                              void* d_out, int out_size)
{
    const float* inputs = (const float*)d_in[0];   // (4,64,512)
    const int*   mask   = (const int*)  d_in[1];   // (4,64)
    const float* Wi     = (const float*)d_in[2];   // (2,2,16384,512)
    const float* Ws     = (const float*)d_in[3];   // (2,2,16384,512)
    const float* bs     = (const float*)d_in[4];   // (2,2,16384)
    const float* Wp     = (const float*)d_in[5];   // (2,2,512,4096)
    float* out = (float*)d_out;                    // (2,4,64,1024)

    const int convBlocks = (int)(WP_ELEMS / 8 / 256);   // 2048

    for (int l = 0; l < NL; l++) {
        const float* Wi_l = Wi + (size_t)l * 2 * NG * ND;
        const float* Ws_l = Ws + (size_t)l * 2 * NG * ND;
        const float* bs_l = bs + (size_t)l * 2 * NG;
        const float* Wp_l = Wp + (size_t)l * 2 * NH * NC;

        init_state_kernel<<<144, 256>>>();              // per-layer state reset
        convert_wp_kernel<<<convBlocks, 256>>>(Wp_l);   // Wp fp32 -> fp16

        dim3 gp(NG / 64, (NB * NT) / 128, 2);
        pi_kernel<<<gp, 256>>>(inputs, Wi_l, l);

        for (int t = 0; t < NT; t++) {
            step_gates_kernel<<<1024, 256>>>(Ws_l, bs_l, mask, t);
            step_proj_kernel<<<1024, 256>>>(mask, t);
        }
        finalize_kernel<<<512, 512>>>(out, l);
    }
}

// round 11
// speedup vs baseline: 1.2920x; 1.1933x over previous
#include <cuda_runtime.h>
#include <cuda_bf16.h>
#include <mma.h>
#include <math.h>

using namespace nvcuda;

// ---------------- problem constants ----------------
#define NL 2          // layers
#define NB 4          // batch
#define NT 64         // time
#define ND 512        // input dim
#define NH 512        // hidden/proj dim
#define NC 4096       // cell dim
#define NG (4*NC)     // 16384 gate rows per dir
#define CLIPV 3.0f
#define WI_ELEMS ((size_t)2 * NG * ND)    // 16,777,216 per layer
#define A_ELEMS  ((size_t)2 * NB * NT * NH) // 262,144 (both dirs)

// ---------------- device scratch (static allocation: allowed) ----------------
__device__ __align__(16) float g_pi[(size_t)2 * NB * NT * NG];   // [dir][b][t][g]  32 MiB
__device__ __align__(16) float g_x [(size_t)2 * NB * NT * NH];   // layer input
__device__ __align__(16) float g_y [(size_t)2 * NB * NT * NH];   // layer raw out
__device__ __align__(16) float g_s [(size_t)2 * NB * NC];        // sigma(o)*tanh(c_new)
__device__ __align__(16) float g_c [(size_t)2 * NB * NC];        // cell state
__device__ __align__(16) float g_h [(size_t)2 * NB * NH];        // hidden state
// split-bf16 (hi/lo) copies for pi GEMM, converted once per layer
__device__ __align__(16) __nv_bfloat16 g_wih[WI_ELEMS];          // 33.5 MB
__device__ __align__(16) __nv_bfloat16 g_wil[WI_ELEMS];          // 33.5 MB
__device__ __align__(16) __nv_bfloat16 g_ah[A_ELEMS];            // 0.5 MB
__device__ __align__(16) __nv_bfloat16 g_al[A_ELEMS];            // 0.5 MB
// proj k-split partials + arrival counters (R4 scheme; counters self-reset)
__device__ __align__(16) float g_pp[(size_t)2 * NH * NB * 8];
__device__ int g_cnt[2 * 64];

__device__ __forceinline__ float dot4(float4 a, float4 b) {
    return a.x*b.x + a.y*b.y + a.z*b.z + a.w*b.w;
}
__device__ __forceinline__ float sigmoidf_(float x) { return 1.0f / (1.0f + expf(-x)); }
__device__ __forceinline__ float clip3(float x)     { return fminf(CLIPV, fmaxf(-CLIPV, x)); }

// ---------------- init: zero h and c (reference resets per layer/direction) ----
__global__ void init_state_kernel() {
    int idx = blockIdx.x * blockDim.x + threadIdx.x;
    if (idx < 2 * NB * NC) g_c[idx] = 0.0f;
    if (idx < 2 * NB * NH) g_h[idx] = 0.0f;
}

// ---------------- conversion: Wi fp32 -> split-bf16 hi/lo (once per layer) -----
__global__ void __launch_bounds__(256)
convert_wi_kernel(const float* __restrict__ Wi_l)
{
    size_t idx = ((size_t)blockIdx.x * 256 + threadIdx.x) * 8;
    if (idx >= WI_ELEMS) return;
    float4 a = __ldcs((const float4*)(Wi_l + idx));
    float4 b = __ldcs((const float4*)(Wi_l + idx + 4));
    float v[8] = {a.x, a.y, a.z, a.w, b.x, b.y, b.z, b.w};
    __align__(16) __nv_bfloat16 hi[8], lo[8];
#pragma unroll
    for (int q = 0; q < 8; q++) {
        hi[q] = __float2bfloat16(v[q]);
        lo[q] = __float2bfloat16(v[q] - __bfloat162float(hi[q]));
    }
    *(uint4*)(g_wih + idx) = *(const uint4*)hi;
    *(uint4*)(g_wil + idx) = *(const uint4*)lo;
}

// ---------------- conversion: A (inputs or g_x) -> split-bf16 hi/lo ------------
__global__ void __launch_bounds__(256)
convert_a_kernel(const float* __restrict__ x0, int l)
{
    size_t idx = ((size_t)blockIdx.x * 256 + threadIdx.x) * 8;
    if (idx >= A_ELEMS) return;
    const size_t d   = idx >> 17;            // 131072 elems per dir
    const size_t off = idx & 131071;
    const float* src = l ? (g_x + (d << 17) + off) : (x0 + off);  // l==0: dirs share A
    float4 a = *(const float4*)src;
    float4 b = *(const float4*)(src + 4);
    float v[8] = {a.x, a.y, a.z, a.w, b.x, b.y, b.z, b.w};
    __align__(16) __nv_bfloat16 hi[8], lo[8];
#pragma unroll
    for (int q = 0; q < 8; q++) {
        hi[q] = __float2bfloat16(v[q]);
        lo[q] = __float2bfloat16(v[q] - __bfloat162float(hi[q]));
    }
    *(uint4*)(g_ah + idx) = *(const uint4*)hi;
    *(uint4*)(g_al + idx) = *(const uint4*)lo;
}

// ---------------- pi GEMM v2: staging = pure uint4 copies of precomputed bf16 ---
// pi[d][m][n] = A[m,:].Wi[n,:] via split-bf16 3-MMA. Tiling identical to R4.
__global__ void __launch_bounds__(256)
pi2_kernel()
{
    const int d = blockIdx.z;
    const __nv_bfloat16* Ah = g_ah + ((size_t)d << 17);
    const __nv_bfloat16* Al = g_al + ((size_t)d << 17);
    const __nv_bfloat16* Bh = g_wih + (size_t)d * NG * ND;
    const __nv_bfloat16* Bl = g_wil + (size_t)d * NG * ND;
    const int mBase = blockIdx.y * 128;
    const int nBase = blockIdx.x * 64;

    __shared__ __align__(16) __nv_bfloat16 As[2][128][40];  // row = 80 B (16B-mult)
    __shared__ __align__(16) __nv_bfloat16 Bs[2][64][40];

    wmma::fragment<wmma::accumulator, 16, 16, 16, float> acc[2][2];
#pragma unroll
    for (int i = 0; i < 2; i++)
#pragma unroll
        for (int j = 0; j < 2; j++) wmma::fill_fragment(acc[i][j], 0.0f);

    const int w  = threadIdx.x >> 5;
    const int wm = w >> 1;
    const int wn = w & 1;

    for (int kk = 0; kk < 16; kk++) {
        const int k0 = kk * 32;
        // A tiles: 128 rows x 32 cols = 4 x 16B segs per row, hi + lo
#pragma unroll
        for (int rpt = 0; rpt < 2; rpt++) {
            int id = threadIdx.x + rpt * 256;   // 0..511
            int r = id >> 2, seg = (id & 3) * 8;
            size_t so = (size_t)(mBase + r) * ND + k0 + seg;
            *(uint4*)&As[0][r][seg] = *(const uint4*)(Ah + so);
            *(uint4*)&As[1][r][seg] = *(const uint4*)(Al + so);
        }
        // B tiles: 64 rows x 32 cols
        {
            int id = threadIdx.x;               // 0..255
            int r = id >> 2, seg = (id & 3) * 8;
            size_t so = (size_t)(nBase + r) * ND + k0 + seg;
            *(uint4*)&Bs[0][r][seg] = *(const uint4*)(Bh + so);
            *(uint4*)&Bs[1][r][seg] = *(const uint4*)(Bl + so);
        }
        __syncthreads();

#pragma unroll
        for (int ks = 0; ks < 2; ks++) {
            wmma::fragment<wmma::matrix_a, 16, 16, 16, __nv_bfloat16, wmma::row_major> ah[2], al[2];
            wmma::fragment<wmma::matrix_b, 16, 16, 16, __nv_bfloat16, wmma::col_major> bh[2], bl[2];
#pragma unroll
            for (int i = 0; i < 2; i++) {
                wmma::load_matrix_sync(ah[i], &As[0][wm * 32 + i * 16][ks * 16], 40);
                wmma::load_matrix_sync(al[i], &As[1][wm * 32 + i * 16][ks * 16], 40);
            }
#pragma unroll
            for (int j = 0; j < 2; j++) {
                wmma::load_matrix_sync(bh[j], &Bs[0][wn * 32 + j * 16][ks * 16], 40);
                wmma::load_matrix_sync(bl[j], &Bs[1][wn * 32 + j * 16][ks * 16], 40);
            }
#pragma unroll
            for (int i = 0; i < 2; i++)
#pragma unroll
                for (int j = 0; j < 2; j++) {
                    wmma::mma_sync(acc[i][j], ah[i], bh[j], acc[i][j]);
                    wmma::mma_sync(acc[i][j], ah[i], bl[j], acc[i][j]);
                    wmma::mma_sync(acc[i][j], al[i], bh[j], acc[i][j]);
                }
        }
        __syncthreads();
    }

#pragma unroll
    for (int i = 0; i < 2; i++)
#pragma unroll
        for (int j = 0; j < 2; j++) {
            float* cp = g_pi + ((size_t)d * (NB * NT) + mBase + wm * 32 + i * 16) * NG
                             + nBase + wn * 32 + j * 16;
            wmma::store_matrix_sync(cp, acc[i][j], NG, wmma::mem_row_major);
        }
}

// ---------------- step 1: gates + cell update (R4 fp32 version, VERBATIM) ------
__global__ void __launch_bounds__(256)
step_gates_kernel(const float* __restrict__ Ws_l,   // (2, 16384, 512)
                  const float* __restrict__ bs_l,   // (2, 16384)
                  const int*   __restrict__ mask, int t)
{
    __shared__ float sh[NB * NH];
    const int d  = blockIdx.x >> 9;
    const int cb = (blockIdx.x & 511) * 8;
    const int td = d ? (NT - 1 - t) : t;
    const int tid = threadIdx.x;

    const float* hsrc = g_h + (size_t)d * NB * NH;
    for (int i = tid; i < NB * NH; i += 256) sh[i] = hsrc[i];
    __syncthreads();

    const int w = tid >> 5, lane = tid & 31;
    const int j = cb + w;
    const float* wbase = Ws_l + (size_t)d * NG * ND;

    float acc[4][4];
#pragma unroll
    for (int q = 0; q < 4; q++)
#pragma unroll
        for (int b = 0; b < 4; b++) acc[q][b] = 0.0f;

#pragma unroll
    for (int it = 0; it < 4; it++) {
        const int k = it * 128 + lane * 4;
        float4 hv0 = *(const float4*)&sh[0 * NH + k];
        float4 hv1 = *(const float4*)&sh[1 * NH + k];
        float4 hv2 = *(const float4*)&sh[2 * NH + k];
        float4 hv3 = *(const float4*)&sh[3 * NH + k];
#pragma unroll
        for (int q = 0; q < 4; q++) {
            float4 wv = *(const float4*)&wbase[(size_t)(q * NC + j) * ND + k];
            acc[q][0] += dot4(wv, hv0);
            acc[q][1] += dot4(wv, hv1);
            acc[q][2] += dot4(wv, hv2);
            acc[q][3] += dot4(wv, hv3);
        }
    }
#pragma unroll
    for (int off = 16; off > 0; off >>= 1)
#pragma unroll
        for (int q = 0; q < 4; q++)
#pragma unroll
            for (int b = 0; b < 4; b++)
                acc[q][b] += __shfl_xor_sync(0xffffffffu, acc[q][b], off);

    if (lane < 4) {
        const int b = lane;
        const float* pib = g_pi + (((size_t)d * NB + b) * NT + td) * NG;
        const float* bsd = bs_l + (size_t)d * NG;
        float gi = acc[0][b] + __ldcs(&pib[0 * NC + j]) + bsd[0 * NC + j];
        float gf = acc[1][b] + __ldcs(&pib[1 * NC + j]) + bsd[1 * NC + j];
        float gg = acc[2][b] + __ldcs(&pib[2 * NC + j]) + bsd[2 * NC + j];
        float go = acc[3][b] + __ldcs(&pib[3 * NC + j]) + bsd[3 * NC + j];

        const size_t ci = ((size_t)d * NB + b) * NC + j;
        float cold = g_c[ci];
        float cn = clip3(sigmoidf_(gi) * tanhf(gg) + sigmoidf_(gf) * cold);
        if (mask[b * NT + td] != 0) g_c[ci] = cn;
        g_s[ci] = sigmoidf_(go) * tanhf(cn);
    }
}

// ---------------- step 2: h_new = clip(s @ Wp^T)  (R4 fp32 K-split, VERBATIM) --
__global__ void __launch_bounds__(256)
step_proj_kernel(const float* __restrict__ Wp_l,    // (2, 512, 4096)
                 const int*   __restrict__ mask, int t)
{
    const int d  = blockIdx.x >> 9;
    const int ig = (blockIdx.x >> 3) & 63;
    const int kc = blockIdx.x & 7;
    const int td = d ? (NT - 1 - t) : t;

    __shared__ float ss[NB * 512];
    const float* sbase = g_s + (size_t)d * NB * NC + kc * 512;
    for (int idx = threadIdx.x; idx < NB * 512; idx += 256) {
        int b = idx >> 9, k = idx & 511;
        ss[idx] = sbase[(size_t)b * NC + k];
    }
    __syncthreads();

    const int w = threadIdx.x >> 5, lane = threadIdx.x & 31;
    const int iOut = ig * 8 + w;
    const float* wrow = Wp_l + ((size_t)d * NH + iOut) * NC + kc * 512;

    float acc[4] = {0.f, 0.f, 0.f, 0.f};
#pragma unroll
    for (int it = 0; it < 4; it++) {
        const int k = it * 128 + lane * 4;
        float4 wv = *(const float4*)&wrow[k];
        acc[0] += dot4(wv, *(const float4*)&ss[0 * 512 + k]);
        acc[1] += dot4(wv, *(const float4*)&ss[1 * 512 + k]);
        acc[2] += dot4(wv, *(const float4*)&ss[2 * 512 + k]);
        acc[3] += dot4(wv, *(const float4*)&ss[3 * 512 + k]);
    }
#pragma unroll
    for (int off = 16; off > 0; off >>= 1)
#pragma unroll
        for (int b = 0; b < 4; b++)
            acc[b] += __shfl_xor_sync(0xffffffffu, acc[b], off);

    if (lane < 4)
        g_pp[(((size_t)d * NH + iOut) * NB + lane) * 8 + kc] = acc[lane];

    __threadfence();
    __syncthreads();
    __shared__ int isLast;
    if (threadIdx.x == 0)
        isLast = (atomicAdd(&g_cnt[d * 64 + ig], 1) == 7);
    __syncthreads();
    if (!isLast) return;

    if (threadIdx.x < 32) {
        const int wi = threadIdx.x >> 2;
        const int b  = threadIdx.x & 3;
        const int io = ig * 8 + wi;
        const float* pp = &g_pp[(((size_t)d * NH + io) * NB + b) * 8];
        float v = 0.0f;
#pragma unroll
        for (int c = 0; c < 8; c++) v += __ldcg(&pp[c]);
        v = clip3(v);
        const size_t yi = (((size_t)d * NB + b) * NT + td) * NH + io;
        if (mask[b * NT + td] != 0) {
            g_h[((size_t)d * NB + b) * NH + io] = v;
            g_y[yi] = v;
        } else {
            g_y[yi] = 0.0f;
        }
    }
    if (threadIdx.x == 0) g_cnt[d * 64 + ig] = 0;
}

// ---------------- finalize layer: skip-add, write output, feed next layer ------
__global__ void __launch_bounds__(512)
finalize_kernel(float* __restrict__ out, int l)
{
    const int idx = blockIdx.x * blockDim.x + threadIdx.x;   // 0 .. 262143
    const int i  = idx & (NH - 1);
    const int tt = (idx >> 9) & (NT - 1);
    const int b  = (idx >> 15) & (NB - 1);
    const int d  = idx >> 17;
    float z = g_y[idx] + (l ? g_x[idx] : 0.0f);
    g_x[idx] = z;
    out[(((size_t)l * NB + b) * NT + tt) * (2 * NH) + d * NH + i] = z;
}

// ---------------- launcher ----------------
extern "C" void kernel_launch(void* const* d_in, const int* in_sizes, int n_in,
                              void* d_out, int out_size)
{
    const float* inputs = (const float*)d_in[0];   // (4,64,512)
    const int*   mask   = (const int*)  d_in[1];   // (4,64)
    const float* Wi     = (const float*)d_in[2];   // (2,2,16384,512)
    const float* Ws     = (const float*)d_in[3];   // (2,2,16384,512)
    const float* bs     = (const float*)d_in[4];   // (2,2,16384)
    const float* Wp     = (const float*)d_in[5];   // (2,2,512,4096)
    float* out = (float*)d_out;                    // (2,4,64,1024)

    const int wiBlocks = (int)(WI_ELEMS / 8 / 256);  // 8192
    const int aBlocks  = (int)(A_ELEMS / 8 / 256);   // 128

    for (int l = 0; l < NL; l++) {
        const float* Wi_l = Wi + (size_t)l * 2 * NG * ND;
        const float* Ws_l = Ws + (size_t)l * 2 * NG * ND;
        const float* bs_l = bs + (size_t)l * 2 * NG;
        const float* Wp_l = Wp + (size_t)l * 2 * NH * NC;

        init_state_kernel<<<144, 256>>>();            // per-layer state reset
        convert_wi_kernel<<<wiBlocks, 256>>>(Wi_l);   // Wi -> split-bf16 hi/lo
        convert_a_kernel<<<aBlocks, 256>>>(inputs, l);

        dim3 gp(NG / 64, (NB * NT) / 128, 2);
        pi2_kernel<<<gp, 256>>>();

        for (int t = 0; t < NT; t++) {
            step_gates_kernel<<<1024, 256>>>(Ws_l, bs_l, mask, t);
            step_proj_kernel<<<1024, 256>>>(Wp_l, mask, t);
        }
        finalize_kernel<<<512, 512>>>(out, l);
    }
}

// round 12
// speedup vs baseline: 1.3493x; 1.0443x over previous
#include <cuda_runtime.h>
#include <cuda_bf16.h>
#include <mma.h>
#include <math.h>

using namespace nvcuda;

// ---------------- problem constants ----------------
#define NL 2          // layers
#define NB 4          // batch
#define NT 64         // time
#define ND 512        // input dim
#define NH 512        // hidden/proj dim
#define NC 4096       // cell dim
#define NG (4*NC)     // 16384 gate rows per dir
#define CLIPV 3.0f
#define WI_ELEMS ((size_t)2 * NG * ND)      // 16,777,216 per layer
#define A_ELEMS  ((size_t)2 * NB * NT * NH) // 262,144 (both dirs)

// ---------------- device scratch (static allocation: allowed) ----------------
__device__ __align__(16) float g_pi[(size_t)2 * NB * NT * NG];   // [dir][b][t][g]  32 MiB
__device__ __align__(16) float g_x [(size_t)2 * NB * NT * NH];   // layer input
__device__ __align__(16) float g_y [(size_t)2 * NB * NT * NH];   // layer raw out
__device__ __align__(16) float g_s [(size_t)2 * NB * NC];        // sigma(o)*tanh(c_new)
__device__ __align__(16) float g_c [(size_t)2 * NB * NC];        // cell state
__device__ __align__(16) float g_h [(size_t)2 * NB * NH];        // hidden state
// split-bf16 (hi/lo) copies for pi GEMM, converted once per layer
__device__ __align__(16) __nv_bfloat16 g_wih[WI_ELEMS];          // 33.5 MB
__device__ __align__(16) __nv_bfloat16 g_wil[WI_ELEMS];          // 33.5 MB
__device__ __align__(16) __nv_bfloat16 g_ah[A_ELEMS];            // 0.5 MB
__device__ __align__(16) __nv_bfloat16 g_al[A_ELEMS];            // 0.5 MB
// proj k-split partials + arrival counters (R4 scheme; counters self-reset)
__device__ __align__(16) float g_pp[(size_t)2 * NH * NB * 8];
__device__ int g_cnt[2 * 64];

__device__ __forceinline__ void pdl_sync() {
#if defined(__CUDA_ARCH__) && (__CUDA_ARCH__ >= 900)
    cudaGridDependencySynchronize();   // wait for PDL predecessor completion
#endif
}

__device__ __forceinline__ float dot4(float4 a, float4 b) {
    return a.x*b.x + a.y*b.y + a.z*b.z + a.w*b.w;
}
__device__ __forceinline__ float sigmoidf_(float x) { return 1.0f / (1.0f + expf(-x)); }
__device__ __forceinline__ float clip3(float x)     { return fminf(CLIPV, fmaxf(-CLIPV, x)); }

// ---------------- init: zero h and c (reference resets per layer/direction) ----
__global__ void init_state_kernel() {
    pdl_sync();   // must not clobber g_c/g_h while previous layer still reads them
    int idx = blockIdx.x * blockDim.x + threadIdx.x;
    if (idx < 2 * NB * NC) g_c[idx] = 0.0f;
    if (idx < 2 * NB * NH) g_h[idx] = 0.0f;
}

// ---------------- conversion: Wi fp32 -> split-bf16 hi/lo (once per layer) -----
__global__ void __launch_bounds__(256)
convert_wi_kernel(const float* __restrict__ Wi_l)
{
    pdl_sync();   // g_wih/g_wil reused across layers (WAR vs previous pi)
    size_t idx = ((size_t)blockIdx.x * 256 + threadIdx.x) * 8;
    if (idx >= WI_ELEMS) return;
    float4 a = __ldcs((const float4*)(Wi_l + idx));
    float4 b = __ldcs((const float4*)(Wi_l + idx + 4));
    float v[8] = {a.x, a.y, a.z, a.w, b.x, b.y, b.z, b.w};
    __align__(16) __nv_bfloat16 hi[8], lo[8];
#pragma unroll
    for (int q = 0; q < 8; q++) {
        hi[q] = __float2bfloat16(v[q]);
        lo[q] = __float2bfloat16(v[q] - __bfloat162float(hi[q]));
    }
    *(uint4*)(g_wih + idx) = *(const uint4*)hi;
    *(uint4*)(g_wil + idx) = *(const uint4*)lo;
}

// ---------------- conversion: A (inputs or g_x) -> split-bf16 hi/lo ------------
__global__ void __launch_bounds__(256)
convert_a_kernel(const float* __restrict__ x0, int l)
{
    pdl_sync();   // reads g_x written by previous finalize
    size_t idx = ((size_t)blockIdx.x * 256 + threadIdx.x) * 8;
    if (idx >= A_ELEMS) return;
    const size_t d   = idx >> 17;            // 131072 elems per dir
    const size_t off = idx & 131071;
    const float* src = l ? (g_x + (d << 17) + off) : (x0 + off);  // l==0: dirs share A
    float4 a = *(const float4*)src;
    float4 b = *(const float4*)(src + 4);
    float v[8] = {a.x, a.y, a.z, a.w, b.x, b.y, b.z, b.w};
    __align__(16) __nv_bfloat16 hi[8], lo[8];
#pragma unroll
    for (int q = 0; q < 8; q++) {
        hi[q] = __float2bfloat16(v[q]);
        lo[q] = __float2bfloat16(v[q] - __bfloat162float(hi[q]));
    }
    *(uint4*)(g_ah + idx) = *(const uint4*)hi;
    *(uint4*)(g_al + idx) = *(const uint4*)lo;
}

// ---------------- pi GEMM v2: staging = pure uint4 copies of precomputed bf16 ---
__global__ void __launch_bounds__(256)
pi2_kernel()
{
    pdl_sync();   // reads g_wih/g_wil/g_ah/g_al; writes g_pi (read by prev layer's gates)
    const int d = blockIdx.z;
    const __nv_bfloat16* Ah = g_ah + ((size_t)d << 17);
    const __nv_bfloat16* Al = g_al + ((size_t)d << 17);
    const __nv_bfloat16* Bh = g_wih + (size_t)d * NG * ND;
    const __nv_bfloat16* Bl = g_wil + (size_t)d * NG * ND;
    const int mBase = blockIdx.y * 128;
    const int nBase = blockIdx.x * 64;

    __shared__ __align__(16) __nv_bfloat16 As[2][128][40];
    __shared__ __align__(16) __nv_bfloat16 Bs[2][64][40];

    wmma::fragment<wmma::accumulator, 16, 16, 16, float> acc[2][2];
#pragma unroll
    for (int i = 0; i < 2; i++)
#pragma unroll
        for (int j = 0; j < 2; j++) wmma::fill_fragment(acc[i][j], 0.0f);

    const int w  = threadIdx.x >> 5;
    const int wm = w >> 1;
    const int wn = w & 1;

    for (int kk = 0; kk < 16; kk++) {
        const int k0 = kk * 32;
#pragma unroll
        for (int rpt = 0; rpt < 2; rpt++) {
            int id = threadIdx.x + rpt * 256;   // 0..511
            int r = id >> 2, seg = (id & 3) * 8;
            size_t so = (size_t)(mBase + r) * ND + k0 + seg;
            *(uint4*)&As[0][r][seg] = *(const uint4*)(Ah + so);
            *(uint4*)&As[1][r][seg] = *(const uint4*)(Al + so);
        }
        {
            int id = threadIdx.x;               // 0..255
            int r = id >> 2, seg = (id & 3) * 8;
            size_t so = (size_t)(nBase + r) * ND + k0 + seg;
            *(uint4*)&Bs[0][r][seg] = *(const uint4*)(Bh + so);
            *(uint4*)&Bs[1][r][seg] = *(const uint4*)(Bl + so);
        }
        __syncthreads();

#pragma unroll
        for (int ks = 0; ks < 2; ks++) {
            wmma::fragment<wmma::matrix_a, 16, 16, 16, __nv_bfloat16, wmma::row_major> ah[2], al[2];
            wmma::fragment<wmma::matrix_b, 16, 16, 16, __nv_bfloat16, wmma::col_major> bh[2], bl[2];
#pragma unroll
            for (int i = 0; i < 2; i++) {
                wmma::load_matrix_sync(ah[i], &As[0][wm * 32 + i * 16][ks * 16], 40);
                wmma::load_matrix_sync(al[i], &As[1][wm * 32 + i * 16][ks * 16], 40);
            }
#pragma unroll
            for (int j = 0; j < 2; j++) {
                wmma::load_matrix_sync(bh[j], &Bs[0][wn * 32 + j * 16][ks * 16], 40);
                wmma::load_matrix_sync(bl[j], &Bs[1][wn * 32 + j * 16][ks * 16], 40);
            }
#pragma unroll
            for (int i = 0; i < 2; i++)
#pragma unroll
                for (int j = 0; j < 2; j++) {
                    wmma::mma_sync(acc[i][j], ah[i], bh[j], acc[i][j]);
                    wmma::mma_sync(acc[i][j], ah[i], bl[j], acc[i][j]);
                    wmma::mma_sync(acc[i][j], al[i], bh[j], acc[i][j]);
                }
        }
        __syncthreads();
    }

#pragma unroll
    for (int i = 0; i < 2; i++)
#pragma unroll
        for (int j = 0; j < 2; j++) {
            float* cp = g_pi + ((size_t)d * (NB * NT) + mBase + wm * 32 + i * 16) * NG
                             + nBase + wn * 32 + j * 16;
            wmma::store_matrix_sync(cp, acc[i][j], NG, wmma::mem_row_major);
        }
}

// ---------------- step 1: gates + cell update (R4 fp32 core + PDL sync) --------
__global__ void __launch_bounds__(256)
step_gates_kernel(const float* __restrict__ Ws_l,   // (2, 16384, 512)
                  const float* __restrict__ bs_l,   // (2, 16384)
                  const int*   __restrict__ mask, int t)
{
    pdl_sync();   // h from proj(t-1), c/s self-chain
    __shared__ float sh[NB * NH];
    const int d  = blockIdx.x >> 9;
    const int cb = (blockIdx.x & 511) * 8;
    const int td = d ? (NT - 1 - t) : t;
    const int tid = threadIdx.x;

    const float* hsrc = g_h + (size_t)d * NB * NH;
    for (int i = tid; i < NB * NH; i += 256) sh[i] = hsrc[i];
    __syncthreads();

    const int w = tid >> 5, lane = tid & 31;
    const int j = cb + w;
    const float* wbase = Ws_l + (size_t)d * NG * ND;

    float acc[4][4];
#pragma unroll
    for (int q = 0; q < 4; q++)
#pragma unroll
        for (int b = 0; b < 4; b++) acc[q][b] = 0.0f;

#pragma unroll
    for (int it = 0; it < 4; it++) {
        const int k = it * 128 + lane * 4;
        float4 hv0 = *(const float4*)&sh[0 * NH + k];
        float4 hv1 = *(const float4*)&sh[1 * NH + k];
        float4 hv2 = *(const float4*)&sh[2 * NH + k];
        float4 hv3 = *(const float4*)&sh[3 * NH + k];
#pragma unroll
        for (int q = 0; q < 4; q++) {
            float4 wv = *(const float4*)&wbase[(size_t)(q * NC + j) * ND + k];
            acc[q][0] += dot4(wv, hv0);
            acc[q][1] += dot4(wv, hv1);
            acc[q][2] += dot4(wv, hv2);
            acc[q][3] += dot4(wv, hv3);
        }
    }
#pragma unroll
    for (int off = 16; off > 0; off >>= 1)
#pragma unroll
        for (int q = 0; q < 4; q++)
#pragma unroll
            for (int b = 0; b < 4; b++)
                acc[q][b] += __shfl_xor_sync(0xffffffffu, acc[q][b], off);

    if (lane < 4) {
        const int b = lane;
        const float* pib = g_pi + (((size_t)d * NB + b) * NT + td) * NG;
        const float* bsd = bs_l + (size_t)d * NG;
        float gi = acc[0][b] + __ldcs(&pib[0 * NC + j]) + bsd[0 * NC + j];
        float gf = acc[1][b] + __ldcs(&pib[1 * NC + j]) + bsd[1 * NC + j];
        float gg = acc[2][b] + __ldcs(&pib[2 * NC + j]) + bsd[2 * NC + j];
        float go = acc[3][b] + __ldcs(&pib[3 * NC + j]) + bsd[3 * NC + j];

        const size_t ci = ((size_t)d * NB + b) * NC + j;
        float cold = g_c[ci];
        float cn = clip3(sigmoidf_(gi) * tanhf(gg) + sigmoidf_(gf) * cold);
        if (mask[b * NT + td] != 0) g_c[ci] = cn;
        g_s[ci] = sigmoidf_(go) * tanhf(cn);
    }
}

// ---------------- step 2: h_new = clip(s @ Wp^T)  (R4 K-split + PDL sync) ------
__global__ void __launch_bounds__(256)
step_proj_kernel(const float* __restrict__ Wp_l,    // (2, 512, 4096)
                 const int*   __restrict__ mask, int t)
{
    pdl_sync();   // s from gates(t)
    const int d  = blockIdx.x >> 9;
    const int ig = (blockIdx.x >> 3) & 63;
    const int kc = blockIdx.x & 7;
    const int td = d ? (NT - 1 - t) : t;

    __shared__ float ss[NB * 512];
    const float* sbase = g_s + (size_t)d * NB * NC + kc * 512;
    for (int idx = threadIdx.x; idx < NB * 512; idx += 256) {
        int b = idx >> 9, k = idx & 511;
        ss[idx] = sbase[(size_t)b * NC + k];
    }
    __syncthreads();

    const int w = threadIdx.x >> 5, lane = threadIdx.x & 31;
    const int iOut = ig * 8 + w;
    const float* wrow = Wp_l + ((size_t)d * NH + iOut) * NC + kc * 512;

    float acc[4] = {0.f, 0.f, 0.f, 0.f};
#pragma unroll
    for (int it = 0; it < 4; it++) {
        const int k = it * 128 + lane * 4;
        float4 wv = *(const float4*)&wrow[k];
        acc[0] += dot4(wv, *(const float4*)&ss[0 * 512 + k]);
        acc[1] += dot4(wv, *(const float4*)&ss[1 * 512 + k]);
        acc[2] += dot4(wv, *(const float4*)&ss[2 * 512 + k]);
        acc[3] += dot4(wv, *(const float4*)&ss[3 * 512 + k]);
    }
#pragma unroll
    for (int off = 16; off > 0; off >>= 1)
#pragma unroll
        for (int b = 0; b < 4; b++)
            acc[b] += __shfl_xor_sync(0xffffffffu, acc[b], off);

    if (lane < 4)
        g_pp[(((size_t)d * NH + iOut) * NB + lane) * 8 + kc] = acc[lane];

    __threadfence();
    __syncthreads();
    __shared__ int isLast;
    if (threadIdx.x == 0)
        isLast = (atomicAdd(&g_cnt[d * 64 + ig], 1) == 7);
    __syncthreads();
    if (!isLast) return;

    if (threadIdx.x < 32) {
        const int wi = threadIdx.x >> 2;
        const int b  = threadIdx.x & 3;
        const int io = ig * 8 + wi;
        const float* pp = &g_pp[(((size_t)d * NH + io) * NB + b) * 8];
        float v = 0.0f;
#pragma unroll
        for (int c = 0; c < 8; c++) v += __ldcg(&pp[c]);
        v = clip3(v);
        const size_t yi = (((size_t)d * NB + b) * NT + td) * NH + io;
        if (mask[b * NT + td] != 0) {
            g_h[((size_t)d * NB + b) * NH + io] = v;
            g_y[yi] = v;
        } else {
            g_y[yi] = 0.0f;
        }
    }
    if (threadIdx.x == 0) g_cnt[d * 64 + ig] = 0;
}

// ---------------- finalize layer: skip-add, write output, feed next layer ------
__global__ void __launch_bounds__(512)
finalize_kernel(float* __restrict__ out, int l)
{
    pdl_sync();   // y from last proj
    const int idx = blockIdx.x * blockDim.x + threadIdx.x;   // 0 .. 262143
    const int i  = idx & (NH - 1);
    const int tt = (idx >> 9) & (NT - 1);
    const int b  = (idx >> 15) & (NB - 1);
    const int d  = idx >> 17;
    float z = g_y[idx] + (l ? g_x[idx] : 0.0f);
    g_x[idx] = z;
    out[(((size_t)l * NB + b) * NT + tt) * (2 * NH) + d * NH + i] = z;
}

// ---------------- PDL launch helper ----------------
template <typename F, typename... Args>
static inline void launch_pdl(F kern, dim3 grid, dim3 block, Args... args)
{
    cudaLaunchConfig_t cfg = {};
    cfg.gridDim = grid;
    cfg.blockDim = block;
    cfg.dynamicSmemBytes = 0;
    cfg.stream = 0;   // legacy default stream (same as <<<>>>; captured by harness)
    cudaLaunchAttribute attr[1];
    attr[0].id = cudaLaunchAttributeProgrammaticStreamSerialization;
    attr[0].val.programmaticStreamSerializationAllowed = 1;
    cfg.attrs = attr;
    cfg.numAttrs = 1;
    cudaLaunchKernelEx(&cfg, kern, args...);
}

// ---------------- launcher ----------------
extern "C" void kernel_launch(void* const* d_in, const int* in_sizes, int n_in,
                              void* d_out, int out_size)
{
    const float* inputs = (const float*)d_in[0];   // (4,64,512)
    const int*   mask   = (const int*)  d_in[1];   // (4,64)
    const float* Wi     = (const float*)d_in[2];   // (2,2,16384,512)
    const float* Ws     = (const float*)d_in[3];   // (2,2,16384,512)
    const float* bs     = (const float*)d_in[4];   // (2,2,16384)
    const float* Wp     = (const float*)d_in[5];   // (2,2,512,4096)
    float* out = (float*)d_out;                    // (2,4,64,1024)

    const int wiBlocks = (int)(WI_ELEMS / 8 / 256);  // 8192
    const int aBlocks  = (int)(A_ELEMS / 8 / 256);   // 128

    for (int l = 0; l < NL; l++) {
        const float* Wi_l = Wi + (size_t)l * 2 * NG * ND;
        const float* Ws_l = Ws + (size_t)l * 2 * NG * ND;
        const float* bs_l = bs + (size_t)l * 2 * NG;
        const float* Wp_l = Wp + (size_t)l * 2 * NH * NC;

        launch_pdl(init_state_kernel, dim3(144), dim3(256));
        launch_pdl(convert_wi_kernel, dim3(wiBlocks), dim3(256), Wi_l);
        launch_pdl(convert_a_kernel, dim3(aBlocks), dim3(256), inputs, l);

        dim3 gp(NG / 64, (NB * NT) / 128, 2);
        launch_pdl(pi2_kernel, gp, dim3(256));

        for (int t = 0; t < NT; t++) {
            launch_pdl(step_gates_kernel, dim3(1024), dim3(256), Ws_l, bs_l, mask, t);
            launch_pdl(step_proj_kernel, dim3(1024), dim3(256), Wp_l, mask, t);
        }
        launch_pdl(finalize_kernel, dim3(512), dim3(512), out, l);
    }
}

// round 13
// speedup vs baseline: 1.6183x; 1.1994x over previous
#include <cuda_runtime.h>
#include <cuda_bf16.h>
#include <mma.h>
#include <math.h>

using namespace nvcuda;

// ---------------- problem constants ----------------
#define NL 2          // layers
#define NB 4          // batch
#define NT 64         // time
#define ND 512        // input dim
#define NH 512        // hidden/proj dim
#define NC 4096       // cell dim
#define NG (4*NC)     // 16384 gate rows per dir
#define CLIPV 3.0f
#define NPART 32      // proj-partial partitions (16 blocks add per partition)
#define WI_ELEMS ((size_t)2 * NG * ND)      // 16,777,216 per layer
#define A_ELEMS  ((size_t)2 * NB * NT * NH) // 262,144 (both dirs)

// ---------------- device scratch (static allocation: allowed) ----------------
__device__ __align__(16) float g_pi[(size_t)2 * NB * NT * NG];   // [dir][b][t][g]  32 MiB
__device__ __align__(16) float g_x [(size_t)2 * NB * NT * NH];   // layer input
__device__ __align__(16) float g_y [(size_t)2 * NB * NT * NH];   // layer raw out
__device__ __align__(16) float g_c [(size_t)2 * NB * NC];        // cell state
__device__ __align__(16) float g_h [(size_t)2 * NB * NH];        // hidden state
// split-bf16 (hi/lo) copies for pi GEMM, converted once per layer
__device__ __align__(16) __nv_bfloat16 g_wih[WI_ELEMS];          // 33.5 MB
__device__ __align__(16) __nv_bfloat16 g_wil[WI_ELEMS];          // 33.5 MB
__device__ __align__(16) __nv_bfloat16 g_ah[A_ELEMS];            // 0.5 MB
__device__ __align__(16) __nv_bfloat16 g_al[A_ELEMS];            // 0.5 MB
// transposed projection weights: g_wpT[d][j][i] = Wp[d][i][j]  (2, 4096, 512)
__device__ __align__(16) float g_wpT[(size_t)2 * NC * NH];       // 16.8 MB
// proj partial accumulators: [parity][partition][(d*NB+b)*NH + i]
// zero-initialized; steady state re-zeroed by hfin after each read
__device__ __align__(16) float g_hpp[2][NPART][2 * NB * NH];     // 1 MB

__device__ __forceinline__ void pdl_sync() {
#if defined(__CUDA_ARCH__) && (__CUDA_ARCH__ >= 900)
    cudaGridDependencySynchronize();   // wait for PDL predecessor completion
#endif
}

__device__ __forceinline__ float dot4(float4 a, float4 b) {
    return a.x*b.x + a.y*b.y + a.z*b.z + a.w*b.w;
}
__device__ __forceinline__ float sigmoidf_(float x) { return 1.0f / (1.0f + expf(-x)); }
__device__ __forceinline__ float clip3(float x)     { return fminf(CLIPV, fmaxf(-CLIPV, x)); }

// ---------------- init: zero h and c (reference resets per layer/direction) ----
__global__ void init_state_kernel() {
    pdl_sync();
    int idx = blockIdx.x * blockDim.x + threadIdx.x;
    if (idx < 2 * NB * NC) g_c[idx] = 0.0f;
    if (idx < 2 * NB * NH) g_h[idx] = 0.0f;
}

// ---------------- conversion: Wi fp32 -> split-bf16 hi/lo (once per layer) -----
__global__ void __launch_bounds__(256)
convert_wi_kernel(const float* __restrict__ Wi_l)
{
    pdl_sync();
    size_t idx = ((size_t)blockIdx.x * 256 + threadIdx.x) * 8;
    if (idx >= WI_ELEMS) return;
    float4 a = __ldcs((const float4*)(Wi_l + idx));
    float4 b = __ldcs((const float4*)(Wi_l + idx + 4));
    float v[8] = {a.x, a.y, a.z, a.w, b.x, b.y, b.z, b.w};
    __align__(16) __nv_bfloat16 hi[8], lo[8];
#pragma unroll
    for (int q = 0; q < 8; q++) {
        hi[q] = __float2bfloat16(v[q]);
        lo[q] = __float2bfloat16(v[q] - __bfloat162float(hi[q]));
    }
    *(uint4*)(g_wih + idx) = *(const uint4*)hi;
    *(uint4*)(g_wil + idx) = *(const uint4*)lo;
}

// ---------------- conversion: A (inputs or g_x) -> split-bf16 hi/lo ------------
__global__ void __launch_bounds__(256)
convert_a_kernel(const float* __restrict__ x0, int l)
{
    pdl_sync();
    size_t idx = ((size_t)blockIdx.x * 256 + threadIdx.x) * 8;
    if (idx >= A_ELEMS) return;
    const size_t d   = idx >> 17;
    const size_t off = idx & 131071;
    const float* src = l ? (g_x + (d << 17) + off) : (x0 + off);
    float4 a = *(const float4*)src;
    float4 b = *(const float4*)(src + 4);
    float v[8] = {a.x, a.y, a.z, a.w, b.x, b.y, b.z, b.w};
    __align__(16) __nv_bfloat16 hi[8], lo[8];
#pragma unroll
    for (int q = 0; q < 8; q++) {
        hi[q] = __float2bfloat16(v[q]);
        lo[q] = __float2bfloat16(v[q] - __bfloat162float(hi[q]));
    }
    *(uint4*)(g_ah + idx) = *(const uint4*)hi;
    *(uint4*)(g_al + idx) = *(const uint4*)lo;
}

// ---------------- transpose Wp: (2,512,4096) -> g_wpT (2,4096,512) -------------
__global__ void __launch_bounds__(256)
transpose_wp_kernel(const float* __restrict__ Wp_l)
{
    pdl_sync();
    __shared__ float tile[32][33];
    const int d = blockIdx.z;
    const int jb = blockIdx.x * 32;   // column base in Wp (j), 0..4095
    const int ib = blockIdx.y * 32;   // row base in Wp (i), 0..511
    const int tx = threadIdx.x & 31, ty = threadIdx.x >> 5;  // 32x8
    const float* src = Wp_l + (size_t)d * NH * NC;
#pragma unroll
    for (int r = 0; r < 4; r++) {
        int i = ib + ty + r * 8;
        tile[ty + r * 8][tx] = src[(size_t)i * NC + jb + tx];
    }
    __syncthreads();
    float* dst = g_wpT + (size_t)d * NC * NH;
#pragma unroll
    for (int r = 0; r < 4; r++) {
        int j = jb + ty + r * 8;
        dst[(size_t)j * NH + ib + tx] = tile[tx][ty + r * 8];
    }
}

// ---------------- pi GEMM v2: staging = pure uint4 copies of precomputed bf16 ---
__global__ void __launch_bounds__(256)
pi2_kernel()
{
    pdl_sync();
    const int d = blockIdx.z;
    const __nv_bfloat16* Ah = g_ah + ((size_t)d << 17);
    const __nv_bfloat16* Al = g_al + ((size_t)d << 17);
    const __nv_bfloat16* Bh = g_wih + (size_t)d * NG * ND;
    const __nv_bfloat16* Bl = g_wil + (size_t)d * NG * ND;
    const int mBase = blockIdx.y * 128;
    const int nBase = blockIdx.x * 64;

    __shared__ __align__(16) __nv_bfloat16 As[2][128][40];
    __shared__ __align__(16) __nv_bfloat16 Bs[2][64][40];

    wmma::fragment<wmma::accumulator, 16, 16, 16, float> acc[2][2];
#pragma unroll
    for (int i = 0; i < 2; i++)
#pragma unroll
        for (int j = 0; j < 2; j++) wmma::fill_fragment(acc[i][j], 0.0f);

    const int w  = threadIdx.x >> 5;
    const int wm = w >> 1;
    const int wn = w & 1;

    for (int kk = 0; kk < 16; kk++) {
        const int k0 = kk * 32;
#pragma unroll
        for (int rpt = 0; rpt < 2; rpt++) {
            int id = threadIdx.x + rpt * 256;
            int r = id >> 2, seg = (id & 3) * 8;
            size_t so = (size_t)(mBase + r) * ND + k0 + seg;
            *(uint4*)&As[0][r][seg] = *(const uint4*)(Ah + so);
            *(uint4*)&As[1][r][seg] = *(const uint4*)(Al + so);
        }
        {
            int id = threadIdx.x;
            int r = id >> 2, seg = (id & 3) * 8;
            size_t so = (size_t)(nBase + r) * ND + k0 + seg;
            *(uint4*)&Bs[0][r][seg] = *(const uint4*)(Bh + so);
            *(uint4*)&Bs[1][r][seg] = *(const uint4*)(Bl + so);
        }
        __syncthreads();

#pragma unroll
        for (int ks = 0; ks < 2; ks++) {
            wmma::fragment<wmma::matrix_a, 16, 16, 16, __nv_bfloat16, wmma::row_major> ah[2], al[2];
            wmma::fragment<wmma::matrix_b, 16, 16, 16, __nv_bfloat16, wmma::col_major> bh[2], bl[2];
#pragma unroll
            for (int i = 0; i < 2; i++) {
                wmma::load_matrix_sync(ah[i], &As[0][wm * 32 + i * 16][ks * 16], 40);
                wmma::load_matrix_sync(al[i], &As[1][wm * 32 + i * 16][ks * 16], 40);
            }
#pragma unroll
            for (int j = 0; j < 2; j++) {
                wmma::load_matrix_sync(bh[j], &Bs[0][wn * 32 + j * 16][ks * 16], 40);
                wmma::load_matrix_sync(bl[j], &Bs[1][wn * 32 + j * 16][ks * 16], 40);
            }
#pragma unroll
            for (int i = 0; i < 2; i++)
#pragma unroll
                for (int j = 0; j < 2; j++) {
                    wmma::mma_sync(acc[i][j], ah[i], bh[j], acc[i][j]);
                    wmma::mma_sync(acc[i][j], ah[i], bl[j], acc[i][j]);
                    wmma::mma_sync(acc[i][j], al[i], bh[j], acc[i][j]);
                }
        }
        __syncthreads();
    }

#pragma unroll
    for (int i = 0; i < 2; i++)
#pragma unroll
        for (int j = 0; j < 2; j++) {
            float* cp = g_pi + ((size_t)d * (NB * NT) + mBase + wm * 32 + i * 16) * NG
                             + nBase + wn * 32 + j * 16;
            wmma::store_matrix_sync(cp, acc[i][j], NG, wmma::mem_row_major);
        }
}

// ---------------- FUSED step: gates + cell update + rank-8 proj partial --------
// grid 1024 = 2 d x 512 cell-groups. Gates core is R4-verbatim; s stays in smem.
// Proj phase: block contributes s[8cells] x wpT[8 rows] to all 512 outputs x 4 b
// via atomicAdd into partition (blk&511)>>4 of the parity-(t&1) accumulator.
__global__ void __launch_bounds__(256, 4)
step_fused_kernel(const float* __restrict__ Ws_l,   // (2, 16384, 512)
                  const float* __restrict__ bs_l,   // (2, 16384)
                  const int*   __restrict__ mask, int t)
{
    pdl_sync();   // h from hfin(t-1); partials zeroed by hfin(t-1) (transitive)
    __shared__ float sh[NB * NH];
    __shared__ float s_sm[8][4];     // s for this block's 8 cells x 4 batches
    const int d  = blockIdx.x >> 9;
    const int cb = (blockIdx.x & 511) * 8;
    const int td = d ? (NT - 1 - t) : t;
    const int tid = threadIdx.x;

    const float* hsrc = g_h + (size_t)d * NB * NH;
    for (int i = tid; i < NB * NH; i += 256) sh[i] = hsrc[i];
    __syncthreads();

    const int w = tid >> 5, lane = tid & 31;
    const int j = cb + w;
    const float* wbase = Ws_l + (size_t)d * NG * ND;

    float acc[4][4];
#pragma unroll
    for (int q = 0; q < 4; q++)
#pragma unroll
        for (int b = 0; b < 4; b++) acc[q][b] = 0.0f;

#pragma unroll
    for (int it = 0; it < 4; it++) {
        const int k = it * 128 + lane * 4;
        float4 hv0 = *(const float4*)&sh[0 * NH + k];
        float4 hv1 = *(const float4*)&sh[1 * NH + k];
        float4 hv2 = *(const float4*)&sh[2 * NH + k];
        float4 hv3 = *(const float4*)&sh[3 * NH + k];
#pragma unroll
        for (int q = 0; q < 4; q++) {
            float4 wv = *(const float4*)&wbase[(size_t)(q * NC + j) * ND + k];
            acc[q][0] += dot4(wv, hv0);
            acc[q][1] += dot4(wv, hv1);
            acc[q][2] += dot4(wv, hv2);
            acc[q][3] += dot4(wv, hv3);
        }
    }
#pragma unroll
    for (int off = 16; off > 0; off >>= 1)
#pragma unroll
        for (int q = 0; q < 4; q++)
#pragma unroll
            for (int b = 0; b < 4; b++)
                acc[q][b] += __shfl_xor_sync(0xffffffffu, acc[q][b], off);

    if (lane < 4) {
        const int b = lane;
        const float* pib = g_pi + (((size_t)d * NB + b) * NT + td) * NG;
        const float* bsd = bs_l + (size_t)d * NG;
        float gi = acc[0][b] + __ldcs(&pib[0 * NC + j]) + bsd[0 * NC + j];
        float gf = acc[1][b] + __ldcs(&pib[1 * NC + j]) + bsd[1 * NC + j];
        float gg = acc[2][b] + __ldcs(&pib[2 * NC + j]) + bsd[2 * NC + j];
        float go = acc[3][b] + __ldcs(&pib[3 * NC + j]) + bsd[3 * NC + j];

        const size_t ci = ((size_t)d * NB + b) * NC + j;
        float cold = g_c[ci];
        float cn = clip3(sigmoidf_(gi) * tanhf(gg) + sigmoidf_(gf) * cold);
        if (mask[b * NT + td] != 0) g_c[ci] = cn;
        s_sm[w][b] = sigmoidf_(go) * tanhf(cn);   // s stays on-chip
    }
    __syncthreads();

    // ---- proj partial: outputs i0 = tid, i1 = tid + 256 (coalesced wpT rows) --
    const float* wpT = g_wpT + (size_t)d * NC * NH + (size_t)cb * NH;
    float pa0[4] = {0.f, 0.f, 0.f, 0.f};
    float pa1[4] = {0.f, 0.f, 0.f, 0.f};
#pragma unroll
    for (int jl = 0; jl < 8; jl++) {
        float w0 = wpT[(size_t)jl * NH + tid];
        float w1 = wpT[(size_t)jl * NH + tid + 256];
#pragma unroll
        for (int b = 0; b < 4; b++) {
            pa0[b] += w0 * s_sm[jl][b];
            pa1[b] += w1 * s_sm[jl][b];
        }
    }
    const int part = (blockIdx.x & 511) >> 4;   // 0..31 (16 blocks per partition)
    float* dst = g_hpp[t & 1][part] + (size_t)d * NB * NH;
#pragma unroll
    for (int b = 0; b < 4; b++) {
        atomicAdd(&dst[b * NH + tid],       pa0[b]);
        atomicAdd(&dst[b * NH + tid + 256], pa1[b]);
    }
}

// ---------------- hfin: sum 32 partials -> clip+mask -> h, y; re-zero partials --
// grid 16 x 256: thread = one (d,b,i) of 4096. Fixed summation order.
__global__ void __launch_bounds__(256)
hfin_kernel(const int* __restrict__ mask, int t)
{
    pdl_sync();   // partials from step_fused(t)
    const int idx = blockIdx.x * 256 + threadIdx.x;   // 0..4095
    const int d = idx >> 11;
    const int b = (idx >> 9) & 3;
    const int i = idx & 511;
    const int td = d ? (NT - 1 - t) : t;
    const int par = t & 1;

    float v = 0.0f;
#pragma unroll
    for (int k = 0; k < NPART; k++) {
        v += g_hpp[par][k][idx];
        g_hpp[par][k][idx] = 0.0f;    // ready for step t+2
    }
    v = clip3(v);
    const size_t yi = (((size_t)d * NB + b) * NT + td) * NH + i;
    if (mask[b * NT + td] != 0) {
        g_h[idx] = v;                 // idx == (d*NB+b)*NH + i
        g_y[yi] = v;
    } else {
        g_y[yi] = 0.0f;
    }
}

// ---------------- finalize layer: skip-add, write output, feed next layer ------
__global__ void __launch_bounds__(512)
finalize_kernel(float* __restrict__ out, int l)
{
    pdl_sync();
    const int idx = blockIdx.x * blockDim.x + threadIdx.x;   // 0 .. 262143
    const int i  = idx & (NH - 1);
    const int tt = (idx >> 9) & (NT - 1);
    const int b  = (idx >> 15) & (NB - 1);
    const int d  = idx >> 17;
    float z = g_y[idx] + (l ? g_x[idx] : 0.0f);
    g_x[idx] = z;
    out[(((size_t)l * NB + b) * NT + tt) * (2 * NH) + d * NH + i] = z;
}

// ---------------- PDL launch helper ----------------
template <typename F, typename... Args>
static inline void launch_pdl(F kern, dim3 grid, dim3 block, Args... args)
{
    cudaLaunchConfig_t cfg = {};
    cfg.gridDim = grid;
    cfg.blockDim = block;
    cfg.dynamicSmemBytes = 0;
    cfg.stream = 0;
    cudaLaunchAttribute attr[1];
    attr[0].id = cudaLaunchAttributeProgrammaticStreamSerialization;
    attr[0].val.programmaticStreamSerializationAllowed = 1;
    cfg.attrs = attr;
    cfg.numAttrs = 1;
    cudaLaunchKernelEx(&cfg, kern, args...);
}

// ---------------- launcher ----------------
extern "C" void kernel_launch(void* const* d_in, const int* in_sizes, int n_in,
                              void* d_out, int out_size)
{
    const float* inputs = (const float*)d_in[0];   // (4,64,512)
    const int*   mask   = (const int*)  d_in[1];   // (4,64)
    const float* Wi     = (const float*)d_in[2];   // (2,2,16384,512)
    const float* Ws     = (const float*)d_in[3];   // (2,2,16384,512)
    const float* bs     = (const float*)d_in[4];   // (2,2,16384)
    const float* Wp     = (const float*)d_in[5];   // (2,2,512,4096)
    float* out = (float*)d_out;                    // (2,4,64,1024)

    const int wiBlocks = (int)(WI_ELEMS / 8 / 256);  // 8192
    const int aBlocks  = (int)(A_ELEMS / 8 / 256);   // 128

    for (int l = 0; l < NL; l++) {
        const float* Wi_l = Wi + (size_t)l * 2 * NG * ND;
        const float* Ws_l = Ws + (size_t)l * 2 * NG * ND;
        const float* bs_l = bs + (size_t)l * 2 * NG;
        const float* Wp_l = Wp + (size_t)l * 2 * NH * NC;

        launch_pdl(init_state_kernel, dim3(144), dim3(256));
        launch_pdl(convert_wi_kernel, dim3(wiBlocks), dim3(256), Wi_l);
        launch_pdl(convert_a_kernel, dim3(aBlocks), dim3(256), inputs, l);
        launch_pdl(transpose_wp_kernel, dim3(128, 16, 2), dim3(256), Wp_l);

        dim3 gp(NG / 64, (NB * NT) / 128, 2);
        launch_pdl(pi2_kernel, gp, dim3(256));

        for (int t = 0; t < NT; t++) {
            launch_pdl(step_fused_kernel, dim3(1024), dim3(256), Ws_l, bs_l, mask, t);
            launch_pdl(hfin_kernel, dim3(16), dim3(256), mask, t);
        }
        launch_pdl(finalize_kernel, dim3(512), dim3(512), out, l);
    }
}